// round 17
// baseline (speedup 1.0000x reference)
#include <cuda_runtime.h>
#include <cuda_fp16.h>

// MedianBlur 5x5, fp32 I/O, 12 images of 1024x1024, zero padding (same).
// Round-17: R16 (8 px/thread, phased column lifetime) + INTERLEAVED merges:
// rows 0,1 -> top merges; rows 3,4 -> bot merges; row 2 -> M; then mid4+fin.
// Peak band liveness 26 -> ~16 h2, total peak ~50 h2 -> far fewer spills at
// the 48-reg cap (256,5). Same CE dag reordered -> bit-identical outputs.

#define IMG_H 1024
#define IMG_W 1024
#define NIMG  12

#define TILE_W 256            // output cols per block (32 threads * 8 px)
#define OUT_H  24             // output rows per block (3 groups of 8)
#define SMEM_H 28             // OUT_H + 4 halo
#define K8     33             // packed-col groups: c = 8k+g, c in [0,264)

typedef __half2 h2;

__device__ __forceinline__ h2 mn2(h2 a, h2 b) { return __hmin2(a, b); }
__device__ __forceinline__ h2 mx2(h2 a, h2 b) { return __hmax2(a, b); }

__device__ __forceinline__ void ce(h2& a, h2& b) {
    h2 t = mn2(a, b);
    b = mx2(a, b);
    a = t;
}

// 9-CE optimal sorting network for 5 elements (ascending), element-wise on half2.
__device__ __forceinline__ void sort5(h2& v0, h2& v1, h2& v2, h2& v3, h2& v4) {
    ce(v0, v1); ce(v3, v4); ce(v2, v4); ce(v2, v3); ce(v0, v3);
    ce(v0, v2); ce(v1, v4); ce(v1, v3); ce(v1, v2);
}

// Constrained merge of top chains, DROPPING rank 0 (provably non-median). 5 ops.
__device__ __forceinline__ void merge_top4(h2 x0, h2 x1, h2 y0, h2 y1, h2 y2,
                                           h2& a1, h2& a2, h2& a3, h2& a4) {
    h2 p = mx2(x0, y0);
    h2 q = mn2(x1, y1);
    a3 = mx2(x1, y1);
    a1 = mn2(p, q);
    a2 = mx2(p, q);
    a4 = y2;
}

// Constrained merge of bottom chains, DROPPING rank 4 (provably non-median). 5 ops.
__device__ __forceinline__ void merge_bot4(h2 x0, h2 x1, h2 y0, h2 y1, h2 y2,
                                           h2& b0, h2& b1, h2& b2, h2& b3) {
    b0 = y0;
    b1 = mn2(x0, y1);
    h2 p = mx2(x0, y1);
    h2 q = mn2(x1, y2);
    b2 = mn2(p, q);
    b3 = mx2(p, q);
}

// Batcher odd-even merge of two sorted 4-chains, ONLY ranks 2..5 of 8. 14 ops.
__device__ __forceinline__ void merge44_mid4(h2 a1, h2 a2, h2 a3, h2 a4,
                                             h2 b0, h2 b1, h2 b2, h2 b3,
                                             h2& s0, h2& s1, h2& s2, h2& s3) {
    h2 t  = mx2(a1, b0);
    h2 u  = mn2(a3, b2);
    h2 E3 = mx2(a3, b2);
    h2 E1 = mn2(t, u);
    h2 E2 = mx2(t, u);
    h2 O0 = mn2(a2, b1);
    h2 t2 = mx2(a2, b1);
    h2 u2 = mn2(a4, b3);
    h2 O1 = mn2(t2, u2);
    h2 O2 = mx2(t2, u2);
    s0 = mx2(O0, E1);
    s1 = mn2(O1, E2);
    s2 = mx2(O1, E2);
    s3 = mn2(O2, E3);
}

// Finisher: med11 == med7({s0<=s1<=s2<=s3} U {m0<=m1<=m2}). 10 ops.
__device__ __forceinline__ h2 med7_fin(h2 s0, h2 s1, h2 s2, h2 s3,
                                       h2 m0, h2 m1, h2 m2) {
    h2 u0 = mx2(s0, m0);
    h2 u3 = mn2(s3, m2);
    h2 p = mn2(u3, m1);
    h2 q = mx2(u3, m1);
    h2 a = mx2(s1, p);
    h2 b = mn2(s2, q);
    h2 lo = mn2(a, b);
    h2 hi = mx2(a, b);
    return mx2(lo, mn2(hi, u0));
}

// Two medians from 6 sorted columns (networks on c0..c4 and c1..c5).
// INTERLEAVED: rows 0,1 -> top merges; rows 3,4 -> bot merges; row 2 -> M;
// then mid4 + finisher. Same dag as rounds 9-16, reordered for liveness.
__device__ __forceinline__ void med_pair(
    const h2 (&c0)[5], const h2 (&c1)[5], const h2 (&c2)[5],
    const h2 (&c3)[5], const h2 (&c4)[5], const h2 (&c5)[5],
    h2& rA, h2& rB) {

    // ---- rows 0,1 -> top chains, merged immediately ----
    h2 aT1, aT2, aT3, aT4, bT1, bT2, bT3, bT4;
    {
        // row 0: top2 of 4, insert -> ranks {3,4}
        h2 a = mn2(c1[0], c2[0]), b = mx2(c1[0], c2[0]);
        h2 c = mn2(c3[0], c4[0]), d = mx2(c3[0], c4[0]);
        h2 q3 = mx2(b, d);
        h2 q2 = mx2(mn2(b, d), mx2(a, c));
        h2 xa = c0[0], xb = c5[0];
        h2 a04 = mx2(q3, xa), a03 = mx2(q2, mn2(q3, xa));
        h2 b04 = mx2(q3, xb), b03 = mx2(q2, mn2(q3, xb));

        // row 1: sort4 minus q0, insert -> ranks {2,3,4}
        h2 v0 = c1[1], v1 = c2[1], v2 = c3[1], v3 = c4[1];
        ce(v0, v1); ce(v2, v3);
        v2 = mx2(v0, v2);
        ce(v1, v3); ce(v1, v2);
        h2 ya = c0[1], yb = c5[1];
        h2 a14 = mx2(v3, ya), a13 = mx2(v2, mn2(v3, ya)), a12 = mx2(v1, mn2(v2, ya));
        h2 b14 = mx2(v3, yb), b13 = mx2(v2, mn2(v3, yb)), b12 = mx2(v1, mn2(v2, yb));

        merge_top4(a03, a04, a12, a13, a14, aT1, aT2, aT3, aT4);
        merge_top4(b03, b04, b12, b13, b14, bT1, bT2, bT3, bT4);
    }

    // ---- rows 3,4 -> bottom chains, merged immediately ----
    h2 aB0, aB1, aB2, aB3, bB0, bB1, bB2, bB3;
    {
        // row 3: sort4 minus q3, insert -> ranks {0,1,2}
        h2 v0 = c1[3], v1 = c2[3], v2 = c3[3], v3 = c4[3];
        ce(v0, v1); ce(v2, v3); ce(v0, v2);
        v1 = mn2(v1, v3);
        ce(v1, v2);
        h2 xa = c0[3], xb = c5[3];
        h2 a30 = mn2(v0, xa), a31 = mx2(v0, mn2(v1, xa)), a32 = mx2(v1, mn2(v2, xa));
        h2 b30 = mn2(v0, xb), b31 = mx2(v0, mn2(v1, xb)), b32 = mx2(v1, mn2(v2, xb));

        // row 4: bottom2 of 4, insert -> ranks {0,1}
        h2 a = mn2(c1[4], c2[4]), b = mx2(c1[4], c2[4]);
        h2 c = mn2(c3[4], c4[4]), d = mx2(c3[4], c4[4]);
        h2 q0 = mn2(a, c);
        h2 q1 = mn2(mx2(a, c), mn2(b, d));
        h2 ya = c0[4], yb = c5[4];
        h2 a40 = mn2(q0, ya), a41 = mx2(q0, mn2(q1, ya));
        h2 b40 = mn2(q0, yb), b41 = mx2(q0, mn2(q1, yb));

        merge_bot4(a40, a41, a30, a31, a32, aB0, aB1, aB2, aB3);
        merge_bot4(b40, b41, b30, b31, b32, bB0, bB1, bB2, bB3);
    }

    // ---- row 2 -> M triples ----
    h2 aM1, aM2, aM3, bM1, bM2, bM3;
    {
        h2 q0 = c1[2], q1 = c2[2], q2 = c3[2], q3 = c4[2];
        ce(q0, q1); ce(q2, q3); ce(q0, q2); ce(q1, q3); ce(q1, q2);
        h2 xa = c0[2], xb = c5[2];
        aM3 = mx2(q2, mn2(q3, xa)); aM2 = mx2(q1, mn2(q2, xa)); aM1 = mx2(q0, mn2(q1, xa));
        bM3 = mx2(q2, mn2(q3, xb)); bM2 = mx2(q1, mn2(q2, xb)); bM1 = mx2(q0, mn2(q1, xb));
    }

    // ---- finals ----
    {
        h2 s0, s1, s2, s3;
        merge44_mid4(aT1, aT2, aT3, aT4, aB0, aB1, aB2, aB3, s0, s1, s2, s3);
        rA = med7_fin(s0, s1, s2, s3, aM1, aM2, aM3);
    }
    {
        h2 s0, s1, s2, s3;
        merge44_mid4(bT1, bT2, bT3, bT4, bB0, bB1, bB2, bB3, s0, s1, s2, s3);
        rB = med7_fin(s0, s1, s2, s3, bM1, bM2, bM3);
    }
}

__global__ __launch_bounds__(256, 5)
void median5x5_h2_kernel(const float* __restrict__ in, float* __restrict__ out) {
    // Packed tile: P4[c] = (h[c], h[c+4]), c = 8k + g, stored pt[r][k][g],
    // g contiguous (32B/group) -> wide LDS. h-col c <-> gx = x0b - 4 + c.
    __shared__ __align__(16) h2 pt[SMEM_H][K8][8];

    const int n   = blockIdx.z;
    const int x0b = blockIdx.x * TILE_W;
    const int y0b = blockIdx.y * OUT_H;
    const float* img = in + (size_t)n * IMG_H * IMG_W;

    const int tx = threadIdx.x;
    const int ty = threadIdx.y;
    const int tid = ty * 32 + tx;

    const bool xin = (x0b >= 4) && (x0b + 267 <= IMG_W - 1);

    if (xin) {
        for (int i = tid; i < SMEM_H * K8; i += 256) {
            const int r = i / K8;
            const int k = i - r * K8;
            const int gy = y0b + r - 2;
            float f[12];
            #pragma unroll
            for (int j = 0; j < 12; j++) f[j] = 0.f;
            if ((unsigned)gy < IMG_H) {
                const float* rowp = img + (size_t)gy * IMG_W + (x0b - 4 + k * 8);
                const float4 fa = *reinterpret_cast<const float4*>(rowp);
                const float4 fb = *reinterpret_cast<const float4*>(rowp + 4);
                const float4 fc = *reinterpret_cast<const float4*>(rowp + 8);
                f[0]=fa.x; f[1]=fa.y; f[2]=fa.z; f[3]=fa.w;
                f[4]=fb.x; f[5]=fb.y; f[6]=fb.z; f[7]=fb.w;
                f[8]=fc.x; f[9]=fc.y; f[10]=fc.z; f[11]=fc.w;
            }
            unsigned wv[8];
            #pragma unroll
            for (int g = 0; g < 8; g++) {
                const h2 p = __float22half2_rn(make_float2(f[g], f[g + 4]));
                wv[g] = *reinterpret_cast<const unsigned*>(&p);
            }
            *reinterpret_cast<uint4*>(&pt[r][k][0]) = make_uint4(wv[0], wv[1], wv[2], wv[3]);
            *reinterpret_cast<uint4*>(&pt[r][k][4]) = make_uint4(wv[4], wv[5], wv[6], wv[7]);
        }
    } else {
        for (int i = tid; i < SMEM_H * K8; i += 256) {
            const int r = i / K8;
            const int k = i - r * K8;
            const int gy = y0b + r - 2;
            const int gx0 = x0b - 4 + k * 8;
            float f[12];
            #pragma unroll
            for (int j = 0; j < 12; j++) f[j] = 0.f;
            if ((unsigned)gy < IMG_H) {
                const float* rowp = img + (size_t)gy * IMG_W;
                if (gx0 >= 0 && gx0 + 11 < IMG_W) {
                    const float4 fa = *reinterpret_cast<const float4*>(rowp + gx0);
                    const float4 fb = *reinterpret_cast<const float4*>(rowp + gx0 + 4);
                    const float4 fc = *reinterpret_cast<const float4*>(rowp + gx0 + 8);
                    f[0]=fa.x; f[1]=fa.y; f[2]=fa.z; f[3]=fa.w;
                    f[4]=fb.x; f[5]=fb.y; f[6]=fb.z; f[7]=fb.w;
                    f[8]=fc.x; f[9]=fc.y; f[10]=fc.z; f[11]=fc.w;
                } else {
                    #pragma unroll
                    for (int j = 0; j < 12; j++)
                        if ((unsigned)(gx0 + j) < IMG_W) f[j] = rowp[gx0 + j];
                }
            }
            unsigned wv[8];
            #pragma unroll
            for (int g = 0; g < 8; g++) {
                const h2 p = __float22half2_rn(make_float2(f[g], f[g + 4]));
                wv[g] = *reinterpret_cast<const unsigned*>(&p);
            }
            *reinterpret_cast<uint4*>(&pt[r][k][0]) = make_uint4(wv[0], wv[1], wv[2], wv[3]);
            *reinterpret_cast<uint4*>(&pt[r][k][4]) = make_uint4(wv[4], wv[5], wv[6], wv[7]);
        }
    }
    __syncthreads();

    // Thread handles pixels p0..p0+7 (p0 = tx*8) as 4 distance-4 pairs.
    // Network column m (m=0..7) is P4[8tx + 2 + m]:
    //   m=0,1  -> pt[row][tx][2..3]     (LDS.64)
    //   m=2..5 -> pt[row][tx][4..7]     (LDS.128)
    //   m=6,7  -> pt[row][tx+1][0..1]   (LDS.64, phase B only)
    #pragma unroll 1
    for (int gr = 0; gr < 3; gr++) {
        const int rb = ty + gr * 8;
        const int y  = y0b + rb;
        if (y >= IMG_H) break;

        // ---- Phase A: columns 0..5 ----
        h2 c0[5], c1[5], c2[5], c3[5], c4[5], c5[5];
        #pragma unroll
        for (int i = 0; i < 5; i++) {
            const uint2 a = *reinterpret_cast<const uint2*>(&pt[rb + i][tx][2]);
            const uint4 b = *reinterpret_cast<const uint4*>(&pt[rb + i][tx][4]);
            c0[i] = *reinterpret_cast<const h2*>(&a.x);
            c1[i] = *reinterpret_cast<const h2*>(&a.y);
            c2[i] = *reinterpret_cast<const h2*>(&b.x);
            c3[i] = *reinterpret_cast<const h2*>(&b.y);
            c4[i] = *reinterpret_cast<const h2*>(&b.z);
            c5[i] = *reinterpret_cast<const h2*>(&b.w);
        }
        sort5(c0[0], c0[1], c0[2], c0[3], c0[4]);
        sort5(c1[0], c1[1], c1[2], c1[3], c1[4]);
        sort5(c2[0], c2[1], c2[2], c2[3], c2[4]);
        sort5(c3[0], c3[1], c3[2], c3[3], c3[4]);
        sort5(c4[0], c4[1], c4[2], c4[3], c4[4]);
        sort5(c5[0], c5[1], c5[2], c5[3], c5[4]);

        h2 rA, rB;
        med_pair(c0, c1, c2, c3, c4, c5, rA, rB);

        // ---- Phase B: columns 6..7 (c0/c1 dead) ----
        h2 c6[5], c7[5];
        #pragma unroll
        for (int i = 0; i < 5; i++) {
            const uint2 c = *reinterpret_cast<const uint2*>(&pt[rb + i][tx + 1][0]);
            c6[i] = *reinterpret_cast<const h2*>(&c.x);
            c7[i] = *reinterpret_cast<const h2*>(&c.y);
        }
        sort5(c6[0], c6[1], c6[2], c6[3], c6[4]);
        sort5(c7[0], c7[1], c7[2], c7[3], c7[4]);

        h2 rC, rD;
        med_pair(c2, c3, c4, c5, c6, c7, rC, rD);

        float4 o0, o1;
        o0.x = __low2float(rA);  o0.y = __low2float(rB);
        o0.z = __low2float(rC);  o0.w = __low2float(rD);
        o1.x = __high2float(rA); o1.y = __high2float(rB);
        o1.z = __high2float(rC); o1.w = __high2float(rD);

        float* orow = out + (size_t)n * IMG_H * IMG_W
                          + (size_t)y * IMG_W + x0b + tx * 8;
        *reinterpret_cast<float4*>(orow)     = o0;
        *reinterpret_cast<float4*>(orow + 4) = o1;
    }
}

extern "C" void kernel_launch(void* const* d_in, const int* in_sizes, int n_in,
                              void* d_out, int out_size) {
    (void)in_sizes; (void)n_in; (void)out_size;
    const float* in = (const float*)d_in[0];
    float* out = (float*)d_out;

    dim3 block(32, 8, 1);
    dim3 grid(IMG_W / TILE_W, (IMG_H + OUT_H - 1) / OUT_H, NIMG);
    median5x5_h2_kernel<<<grid, block>>>(in, out);
}